// round 17
// baseline (speedup 1.0000x reference)
#include <cuda_runtime.h>
#include <cuda_fp16.h>
#include <math.h>
#include <stdint.h>

#define L_SEQ 2048
#define B_SZ  16
#define H_DIM 512
#define NS    32
#define BH    (B_SZ*H_DIM)
#define LBH   (L_SEQ*B_SZ*H_DIM)

__device__ __half g_unh[LBH];             // LN output, (L,B,H) fp16
__device__ __half g_ut[LBH];              // LN output, (B,H,L) fp16
__device__ __half g_yhl[LBH];             // gelu out, (B,H,L) fp16 (GEMM A, k-major rows)
__device__ __half g_wh[2*H_DIM*H_DIM];    // W conv, fp16
__device__ float g_rr[H_DIM*NS], g_ri[H_DIM*NS], g_cr[H_DIM*NS], g_ci[H_DIM*NS];
__device__ __half g_M[H_DIM*32*96];       // per-h [T(32x32) | P(32x64)]
__device__ __half g_Wm[H_DIM*64*32];      // per-h state-hop matrix
__device__ float  g_r32[H_DIM*NS*2];      // per-(h,n) r^32

__device__ __forceinline__ uint32_t smem_u32(const void* p) {
    uint32_t a;
    asm("{ .reg .u64 t; cvta.to.shared.u64 t, %1; cvt.u32.u64 %0, t; }" : "=r"(a) : "l"(p));
    return a;
}
#define LDM_X4(r0,r1,r2,r3,addr) \
    asm volatile("ldmatrix.sync.aligned.m8n8.x4.shared.b16 {%0,%1,%2,%3}, [%4];" \
        : "=r"(r0), "=r"(r1), "=r"(r2), "=r"(r3) : "r"(addr))
#define LDM_X4_T(r0,r1,r2,r3,addr) \
    asm volatile("ldmatrix.sync.aligned.m8n8.x4.trans.shared.b16 {%0,%1,%2,%3}, [%4];" \
        : "=r"(r0), "=r"(r1), "=r"(r2), "=r"(r3) : "r"(addr))
#define MMA16816(c0,c1,c2,c3,a0,a1,a2,a3,b0,b1) \
    asm volatile("mma.sync.aligned.m16n8k16.row.col.f32.f16.f16.f32 " \
        "{%0,%1,%2,%3}, {%4,%5,%6,%7}, {%8,%9}, {%0,%1,%2,%3};" \
        : "+f"(c0), "+f"(c1), "+f"(c2), "+f"(c3) \
        : "r"(a0), "r"(a1), "r"(a2), "r"(a3), "r"(b0), "r"(b1))

// ---------------- K0: SSM constants ----------------
__global__ void const_kernel(const float* __restrict__ log_dt, const float* __restrict__ C,
                             const float* __restrict__ log_A_real, const float* __restrict__ A_imag) {
    int idx = blockIdx.x*blockDim.x + threadIdx.x;
    if (idx >= H_DIM*NS) return;
    int h = idx >> 5;
    float dt  = expf(log_dt[h]);
    float Are = -expf(log_A_real[idx]);
    float Aim = A_imag[idx];
    float er  = expf(Are*dt);
    float rr  = er*cosf(Aim*dt), ri = er*sinf(Aim*dt);
    float nre = rr - 1.f, nim = ri;
    float den = Are*Are + Aim*Aim;
    float qre = (nre*Are + nim*Aim)/den;
    float qim = (nim*Are - nre*Aim)/den;
    float Cre = C[2*idx], Cim = C[2*idx+1];
    g_rr[idx] = rr;  g_ri[idx] = ri;
    g_cr[idx] = 2.f*(Cre*qre - Cim*qim);
    g_ci[idx] = -2.f*(Cre*qim + Cim*qre);
}

// ---------------- K0b: build per-h T/P/W matrices ---------------------------
__global__ void mat_kernel() {     // grid 512, block 32
    __shared__ float kap[32];
    int h = blockIdx.x, n = threadIdx.x;
    float rr = g_rr[h*NS+n], ri = g_ri[h*NS+n];
    float cr = g_cr[h*NS+n], ci = g_ci[h*NS+n];
    float Rre = 1.f, Rim = 0.f;            // r^0
    __half* Mh = g_M  + h*32*96;
    __half* Wh = g_Wm + h*64*32;
    for (int d = 0; d < 32; d++) {
        float kv = cr*Rre + ci*Rim;        // kappa[d] uses r^d
        #pragma unroll
        for (int o = 16; o >= 1; o >>= 1) kv += __shfl_xor_sync(0xffffffffu, kv, o);
        if (n == 0) kap[d] = kv;
        Wh[(2*n)*32   + (31-d)] = __float2half_rn(Rre);
        Wh[(2*n+1)*32 + (31-d)] = __float2half_rn(Rim);
        float nR = Rre*rr - Rim*ri, nI = Rre*ri + Rim*rr;
        Rre = nR; Rim = nI;                // now r^{d+1}
        Mh[d*96 + 32 + 2*n]   = __float2half_rn(cr*Rre + ci*Rim);   // P[t=d]
        Mh[d*96 + 32 + 2*n+1] = __float2half_rn(ci*Rre - cr*Rim);
    }
    g_r32[(h*NS+n)*2]   = Rre;
    g_r32[(h*NS+n)*2+1] = Rim;
    __syncwarp();
    for (int j = 0; j < 32; j++)
        Mh[n*96 + j] = (j <= n) ? __float2half_rn(kap[n-j]) : __float2half_rn(0.f);
}

// W conv -> fp16
__global__ void wcvt_kernel(const float* __restrict__ Wm) {
    int i = blockIdx.x*blockDim.x + threadIdx.x;
    g_wh[i] = __float2half_rn(Wm[i]);
}

// ---------------- K1: LayerNorm over H, fp16 out ----------------------------
__global__ void ln_kernel(const float* __restrict__ u, const float* __restrict__ lnw,
                          const float* __restrict__ lnb) {
    int warp = (blockIdx.x*blockDim.x + threadIdx.x) >> 5;
    int lane = threadIdx.x & 31;
    const float4* row = (const float4*)(u + (size_t)warp*H_DIM);
    float4 v[4];
    float s = 0.f, sq = 0.f;
    #pragma unroll
    for (int i = 0; i < 4; i++) {
        float4 x = row[lane + i*32];
        v[i] = x;
        s  += x.x + x.y + x.z + x.w;
        sq += x.x*x.x + x.y*x.y + x.z*x.z + x.w*x.w;
    }
    #pragma unroll
    for (int o = 16; o >= 1; o >>= 1) {
        s  += __shfl_xor_sync(0xffffffffu, s,  o);
        sq += __shfl_xor_sync(0xffffffffu, sq, o);
    }
    float mu = s*(1.f/H_DIM);
    float rstd = rsqrtf(sq*(1.f/H_DIM) - mu*mu + 1e-5f);
    const float4* w4 = (const float4*)lnw;
    const float4* b4 = (const float4*)lnb;
    __half* orow = g_unh + (size_t)warp*H_DIM;
    #pragma unroll
    for (int i = 0; i < 4; i++) {
        int c = lane + i*32;
        float4 wv = w4[c], bv = b4[c];
        __half2 p0 = __floats2half2_rn((v[i].x - mu)*rstd*wv.x + bv.x,
                                       (v[i].y - mu)*rstd*wv.y + bv.y);
        __half2 p1 = __floats2half2_rn((v[i].z - mu)*rstd*wv.z + bv.z,
                                       (v[i].w - mu)*rstd*wv.w + bv.w);
        uint2 val;
        val.x = *(uint32_t*)&p0; val.y = *(uint32_t*)&p1;
        *(uint2*)(orow + 4*c) = val;
    }
}

// ---------------- T1: (L,B,H) fp16 -> (B,H,L) fp16 --------------------------
__global__ void t1_kernel() {      // grid (64,16,16), block (32,8)
    __shared__ __half sm[32][34];
    int l0 = blockIdx.x*32, h0 = blockIdx.y*32, b = blockIdx.z;
    int tx = threadIdx.x, ty = threadIdx.y;
    #pragma unroll
    for (int i = 0; i < 4; i++)
        sm[ty+8*i][tx] = g_unh[(size_t)(l0+ty+8*i)*BH + b*H_DIM + h0 + tx];
    __syncthreads();
    #pragma unroll
    for (int i = 0; i < 4; i++)
        g_ut[((size_t)b*H_DIM + h0+ty+8*i)*L_SEQ + l0 + tx] = sm[tx][ty+8*i];
}

// ---------------- K2: fused chunked scan on tensor cores (R16, unchanged) ---
__global__ void __launch_bounds__(128, 5) scan_mega(const float* __restrict__ Dp) {
    __shared__ __half Us[64][40];          // [chunk][j]
    __shared__ __half Ms[32][104];         // [t][k 0..95]
    __shared__ __half Ws[64][40];          // [2n][j]
    __shared__ __half Ds[64][72];          // [2n][chunk]
    __shared__ __half Ss[64][72];          // [chunk][2n]
    __shared__ __align__(16) __half Ys[2048];
    int h = blockIdx.x;
    int tid = threadIdx.x, w = tid >> 5, lane = tid & 31;
    int g = lane >> 2, tq = lane & 3;
    float Dh = Dp[h];

    {   // stage M (3072 halves), W (2048) once
        const uint32_t* ms = (const uint32_t*)(g_M + h*32*96);
        for (int i = tid; i < 1536; i += 128) {
            int s = i*2, r = s/96, cpos = s - r*96;
            *(uint32_t*)&Ms[r][cpos] = ms[i];
        }
        const uint32_t* ws = (const uint32_t*)(g_Wm + h*64*32);
        for (int i = tid; i < 1024; i += 128) {
            int s = i*2, r = s >> 5, cpos = s & 31;
            *(uint32_t*)&Ws[r][cpos] = ws[i];
        }
    }

    for (int ib = 0; ib < 4; ib++) {
        int b = blockIdx.y*4 + ib;
        {   // stage U (2048 halves)
            const uint32_t* us = (const uint32_t*)(g_ut + ((size_t)b*H_DIM + h)*L_SEQ);
            for (int i = tid; i < 1024; i += 128) {
                int s = i*2, ch = s >> 5, j = s & 31;
                *(uint32_t*)&Us[ch][j] = us[i];
            }
        }
        __syncthreads();

        {   // Phase 1: D = W @ U^T   (M=64, N=16/warp, K=32)
            float cd[4][2][4];
            #pragma unroll
            for (int i = 0; i < 4; i++)
                #pragma unroll
                for (int j = 0; j < 2; j++)
                    #pragma unroll
                    for (int q = 0; q < 4; q++) cd[i][j][q] = 0.f;
            #pragma unroll
            for (int ks = 0; ks < 2; ks++) {
                int kk = ks*16;
                uint32_t a[4][4], bb[4];
                #pragma unroll
                for (int mt = 0; mt < 4; mt++) {
                    int row = mt*16 + (lane & 7) + ((lane >> 3) & 1)*8;
                    int col = kk + (lane >> 4)*8;
                    LDM_X4(a[mt][0], a[mt][1], a[mt][2], a[mt][3], smem_u32(&Ws[row][col]));
                }
                {
                    int row = w*16 + (lane & 7) + ((lane >= 16) ? 8 : 0);
                    int col = kk + ((lane >> 3) & 1)*8;
                    LDM_X4(bb[0], bb[1], bb[2], bb[3], smem_u32(&Us[row][col]));
                }
                #pragma unroll
                for (int mt = 0; mt < 4; mt++)
                    #pragma unroll
                    for (int nt = 0; nt < 2; nt++)
                        MMA16816(cd[mt][nt][0], cd[mt][nt][1], cd[mt][nt][2], cd[mt][nt][3],
                                 a[mt][0], a[mt][1], a[mt][2], a[mt][3], bb[nt*2], bb[nt*2+1]);
            }
            #pragma unroll
            for (int mt = 0; mt < 4; mt++)
                #pragma unroll
                for (int nt = 0; nt < 2; nt++)
                    #pragma unroll
                    for (int q = 0; q < 4; q++) {
                        int row = mt*16 + g + ((q >> 1) ? 8 : 0);
                        int col = w*16 + nt*8 + 2*tq + (q & 1);
                        Ds[row][col] = __float2half_rn(cd[mt][nt][q]);
                    }
        }
        __syncthreads();

        if (w == 0) {   // Phase 2: sequential state hop (lane = n)
            int n = lane;
            float r32r = g_r32[(h*NS+n)*2], r32i = g_r32[(h*NS+n)*2+1];
            float sre = 0.f, sim = 0.f;
            for (int c = 0; c < 64; c++) {
                Ss[c][2*n]   = __float2half_rn(sre);
                Ss[c][2*n+1] = __float2half_rn(sim);
                float dre = __half2float(Ds[2*n][c]);
                float dim = __half2float(Ds[2*n+1][c]);
                float nr = fmaf(r32r, sre, fmaf(-r32i, sim, dre));
                float ni = fmaf(r32r, sim, fmaf(r32i, sre, dim));
                sre = nr; sim = ni;
            }
        }
        __syncthreads();

        {   // Phase 3: Y = M @ [U;S]^T  (M=32, N=16/warp, K=96)
            float cy[2][2][4];
            #pragma unroll
            for (int i = 0; i < 2; i++)
                #pragma unroll
                for (int j = 0; j < 2; j++)
                    #pragma unroll
                    for (int q = 0; q < 4; q++) cy[i][j][q] = 0.f;
            #pragma unroll
            for (int ks = 0; ks < 6; ks++) {
                int kk = ks*16;
                uint32_t a[2][4], bb[4];
                #pragma unroll
                for (int mt = 0; mt < 2; mt++) {
                    int row = mt*16 + (lane & 7) + ((lane >> 3) & 1)*8;
                    int col = kk + (lane >> 4)*8;
                    LDM_X4(a[mt][0], a[mt][1], a[mt][2], a[mt][3], smem_u32(&Ms[row][col]));
                }
                {
                    int row = w*16 + (lane & 7) + ((lane >= 16) ? 8 : 0);
                    int col = ((lane >> 3) & 1)*8;
                    uint32_t ad = (ks < 2) ? smem_u32(&Us[row][kk + col])
                                           : smem_u32(&Ss[row][kk - 32 + col]);
                    LDM_X4(bb[0], bb[1], bb[2], bb[3], ad);
                }
                #pragma unroll
                for (int mt = 0; mt < 2; mt++)
                    #pragma unroll
                    for (int nt = 0; nt < 2; nt++)
                        MMA16816(cy[mt][nt][0], cy[mt][nt][1], cy[mt][nt][2], cy[mt][nt][3],
                                 a[mt][0], a[mt][1], a[mt][2], a[mt][3], bb[nt*2], bb[nt*2+1]);
            }
            #pragma unroll
            for (int mt = 0; mt < 2; mt++)
                #pragma unroll
                for (int nt = 0; nt < 2; nt++)
                    #pragma unroll
                    for (int q = 0; q < 4; q++) {
                        int trow = mt*16 + g + ((q >> 1) ? 8 : 0);
                        int ch   = w*16 + nt*8 + 2*tq + (q & 1);
                        float uv = __half2float(Us[ch][trow]);
                        float yd = cy[mt][nt][q] + Dh*uv;
                        float ge = 0.5f*yd*(1.f + erff(yd*0.70710678118f));
                        Ys[ch*32 + trow] = __float2half_rn(ge);
                    }
        }
        __syncthreads();
        {
            uint32_t* dst = (uint32_t*)(g_yhl + ((size_t)b*H_DIM + h)*L_SEQ);
            const uint32_t* src = (const uint32_t*)Ys;
            for (int i = tid; i < 1024; i += 128) dst[i] = src[i];
        }
    }
}

// ---------------- K3: mma.sync fp16 GEMM + GLU + residual -------------------
// CTA 128 l x 128 o-cols, FOUR warps, warp tile 64x64 (2x FLOP per ldmatrix
// byte vs 64x32 -> smem crossbar no longer binds). 4-stage ring, 1 sync/stage,
// 3-stage cp.async lookahead. smem 74KB -> 2 CTA/SM.
#define NKT    16
#define NSTG   4
#define A_H    (32*136)
#define B_H    (128*40)
#define SMEM_BYTES (NSTG*(A_H + B_H)*2)

__global__ void __launch_bounds__(128, 2) mma_gemm(const float* __restrict__ bconv,
                                                   const float* __restrict__ u,
                                                   float* __restrict__ out) {
    extern __shared__ __half smh[];
    __half* Abuf = smh;
    __half* Bbuf = smh + NSTG*A_H;
    int tid = threadIdx.x;
    int l0 = blockIdx.x*128, h0 = blockIdx.y*64, b = blockIdx.z;
    int wid = tid >> 5, lane = tid & 31;
    int wm = wid & 1, wn = wid >> 1;        // wm: l-half(64), wn: col-half(64)
    int g = lane >> 2, t = lane & 3;
    const __half* Abase = g_yhl + (size_t)b*H_DIM*L_SEQ + l0;   // row k, col l

    float c[4][8][4];
    #pragma unroll
    for (int i = 0; i < 4; i++)
        #pragma unroll
        for (int j = 0; j < 8; j++)
            #pragma unroll
            for (int q = 0; q < 4; q++) c[i][j][q] = 0.f;

    auto load_stage = [&](int kt, int s) {
        int k0 = kt*32;
        __half* As = Abuf + s*A_H;
        __half* Bs = Bbuf + s*B_H;
        #pragma unroll
        for (int p = 0; p < 4; p++) {       // A: 32 k-rows x 128 l = 512 x 16B
            int idx = tid + p*128;
            int r = idx >> 4, seg = idx & 15;
            const __half* srcA = Abase + (size_t)(k0 + r)*L_SEQ + seg*8;
            uint32_t dstA = smem_u32(As + r*136 + seg*8);
            asm volatile("cp.async.cg.shared.global [%0], [%1], 16;" :: "r"(dstA), "l"(srcA));
        }
        #pragma unroll
        for (int p = 0; p < 4; p++) {       // B: 128 o-rows x 32 k = 512 x 16B
            int idx = tid + p*128;
            int r = idx >> 2, seg = idx & 3;
            int orow = (r & 1) ? (H_DIM + h0 + (r >> 1)) : (h0 + (r >> 1));
            const __half* srcB = g_wh + (size_t)orow*H_DIM + k0 + seg*8;
            uint32_t dstB = smem_u32(Bs + r*40 + seg*8);
            asm volatile("cp.async.cg.shared.global [%0], [%1], 16;" :: "r"(dstB), "l"(srcB));
        }
    };
    auto compute = [&](int s) {
        const __half* As = Abuf + s*A_H;
        const __half* Bs = Bbuf + s*B_H;
        #pragma unroll
        for (int kk = 0; kk < 32; kk += 16) {
            uint32_t a[4][4], bb[4][4];
            #pragma unroll
            for (int mt = 0; mt < 4; mt++) {   // A via trans: addr row = k, col = l
                int kr = kk + (lane & 7) + ((lane >> 4) & 1)*8;
                int lc = wm*64 + mt*16 + ((lane >> 3) & 1)*8;
                LDM_X4_T(a[mt][0], a[mt][1], a[mt][2], a[mt][3], smem_u32(As + kr*136 + lc));
            }
            #pragma unroll
            for (int ntp = 0; ntp < 4; ntp++) {
                int row = wn*64 + ntp*16 + (lane & 7) + ((lane >= 16) ? 8 : 0);
                int col = kk + ((lane >> 3) & 1)*8;
                LDM_X4(bb[ntp][0], bb[ntp][1], bb[ntp][2], bb[ntp][3], smem_u32(Bs + row*40 + col));
            }
            #pragma unroll
            for (int mt = 0; mt < 4; mt++)
                #pragma unroll
                for (int nt = 0; nt < 8; nt++) {
                    int ntp = nt >> 1, hh = nt & 1;
                    MMA16816(c[mt][nt][0], c[mt][nt][1], c[mt][nt][2], c[mt][nt][3],
                             a[mt][0], a[mt][1], a[mt][2], a[mt][3],
                             bb[ntp][hh*2], bb[ntp][hh*2+1]);
                }
        }
    };

    #pragma unroll
    for (int s = 0; s < NSTG-1; s++) {      // prologue: 3 stages in flight
        load_stage(s, s);
        asm volatile("cp.async.commit_group;");
    }
    int sidx = 0, lidx = NSTG-1;
    for (int kt = 0; kt < NKT; kt++) {
        asm volatile("cp.async.wait_group 2;");   // stage kt resident
        __syncthreads();
        if (kt + NSTG-1 < NKT) load_stage(kt + NSTG-1, lidx);
        asm volatile("cp.async.commit_group;");   // (possibly empty) group
        compute(sidx);
        if (++sidx == NSTG) sidx = 0;
        if (++lidx == NSTG) lidx = 0;
    }

    // Epilogue: c0/c1 = (a,g) at (l, h); c2/c3 at (l+8, h)
    #pragma unroll
    for (int mt = 0; mt < 4; mt++) {
        #pragma unroll
        for (int nt = 0; nt < 8; nt++) {
            int h = h0 + wn*32 + nt*4 + t;
            float bA = bconv[h], bG = bconv[H_DIM + h];
            #pragma unroll
            for (int r2 = 0; r2 < 2; r2++) {
                int l = l0 + wm*64 + mt*16 + g + r2*8;
                float av = c[mt][nt][r2*2+0] + bA;
                float gv = c[mt][nt][r2*2+1] + bG;
                size_t o = (size_t)l*BH + (size_t)b*H_DIM + h;
                out[o] = u[o] + av * (1.f/(1.f + __expf(-gv)));
            }
        }
    }
}

// ---------------------------------------------------------------------------
extern "C" void kernel_launch(void* const* d_in, const int* in_sizes, int n_in,
                              void* d_out, int out_size) {
    const float* u          = (const float*)d_in[0];
    const float* log_dt     = (const float*)d_in[1];
    const float* C          = (const float*)d_in[2];
    const float* log_A_real = (const float*)d_in[3];
    const float* A_imag     = (const float*)d_in[4];
    const float* D          = (const float*)d_in[5];
    const float* Wm         = (const float*)d_in[6];
    const float* b_conv     = (const float*)d_in[7];
    const float* ln_w       = (const float*)d_in[8];
    const float* ln_b       = (const float*)d_in[9];
    float* out = (float*)d_out;

    cudaFuncSetAttribute(mma_gemm, cudaFuncAttributeMaxDynamicSharedMemorySize, SMEM_BYTES);

    const_kernel<<<64, 256>>>(log_dt, C, log_A_real, A_imag);
    mat_kernel<<<512, 32>>>();
    wcvt_kernel<<<512, 1024>>>(Wm);
    ln_kernel<<<(L_SEQ*B_SZ)/8, 256>>>(u, ln_w, ln_b);
    t1_kernel<<<dim3(64, 16, 16), dim3(32, 8)>>>();
    scan_mega<<<dim3(H_DIM, B_SZ/4), 128>>>(D);
    mma_gemm<<<dim3(L_SEQ/128, H_DIM/64, B_SZ), 128, SMEM_BYTES>>>(b_conv, u, out);
}